// round 5
// baseline (speedup 1.0000x reference)
#include <cuda_runtime.h>
#include <math.h>

#define KSZ 7
#define PAD 3

#define B_  8
#define T_  16
#define C_  256
#define HW_ 784
#define HW4_ 196          // HW_/4 (float4)
#define NBC (B_ * C_)     // 2048
#define PSROW (T_ + 2 * PAD + 1)   // 23

// Scratch (no allocations allowed)
__device__ float d_pooled[B_ * C_ * T_];      // [b][c][t]
__device__ float d_Kern[B_ * C_ * KSZ];       // [b][c][k]
__device__ float d_Yt[B_ * T_ * 64];          // [b][t][o]

// ---------------------------------------------------------------------------
// Kernel 1: spatial mean pool. One warp per (b,t,c) row (784 contiguous f32).
// ---------------------------------------------------------------------------
__global__ void pool_kernel(const float* __restrict__ x) {
    const int warp = threadIdx.x >> 5;
    const int lane = threadIdx.x & 31;
    const int row  = blockIdx.x * 8 + warp;       // (b*T + t)*C + c
    const float4* xr = reinterpret_cast<const float4*>(x) + (size_t)row * HW4_;

    float s = 0.f;
    #pragma unroll 7
    for (int i = lane; i < HW4_; i += 32) {
        float4 v = xr[i];
        s += (v.x + v.y) + (v.z + v.w);
    }
    #pragma unroll
    for (int o = 16; o > 0; o >>= 1) s += __shfl_xor_sync(0xffffffffu, s, o);

    if (lane == 0) {
        int c  = row & (C_ - 1);
        int bt = row >> 8;
        int t  = bt & (T_ - 1);
        int b  = bt >> 4;
        d_pooled[(b * C_ + c) * T_ + t] = s * (1.0f / (float)HW_);
    }
}

// ---------------------------------------------------------------------------
// Kernel 2: fused coefficients. Grid = (65, 8), 128 threads.
//   blockIdx.x < 64 : conv1d output channel o for batch b  -> d_Yt[b][t][o]
//   blockIdx.x == 64: G branch for batch b (2 channels per thread) -> d_Kern
// ---------------------------------------------------------------------------
__global__ void coeff_kernel(const float* __restrict__ Wl1,   // [64][256][7]
                             const float* __restrict__ W1,    // [32][16]
                             const float* __restrict__ W2)    // [7][32]
{
    __shared__ float ps[C_ * PSROW];
    __shared__ float red[4][T_];
    __shared__ float w1s[32 * 16];
    __shared__ float w2s[7 * 32];

    const int b   = blockIdx.y;
    const int tid = threadIdx.x;          // 0..127

    if (blockIdx.x == 64) {
        // ---- G branch ----
        for (int i = tid; i < 512; i += 128) w1s[i] = W1[i];
        for (int i = tid; i < 224; i += 128) w2s[i] = W2[i];
        __syncthreads();

        #pragma unroll
        for (int cc = 0; cc < 2; cc++) {
            const int c = tid + cc * 128;
            float p[T_];
            const float4* pp = reinterpret_cast<const float4*>(d_pooled + (b * C_ + c) * T_);
            #pragma unroll
            for (int q = 0; q < 4; q++) {
                float4 v = pp[q];
                p[q*4+0]=v.x; p[q*4+1]=v.y; p[q*4+2]=v.z; p[q*4+3]=v.w;
            }
            float s[KSZ];
            #pragma unroll
            for (int k = 0; k < KSZ; k++) s[k] = 0.f;
            for (int u = 0; u < 32; u++) {
                float acc = 0.f;
                #pragma unroll
                for (int t = 0; t < T_; t++) acc += p[t] * w1s[u * 16 + t];
                float g = tanhf(acc);
                #pragma unroll
                for (int k = 0; k < KSZ; k++) s[k] += g * w2s[k * 32 + u];
            }
            float m = s[0];
            #pragma unroll
            for (int k = 1; k < KSZ; k++) m = fmaxf(m, s[k]);
            float e[KSZ], sum = 0.f;
            #pragma unroll
            for (int k = 0; k < KSZ; k++) { e[k] = expf(s[k] - m); sum += e[k]; }
            float inv = 1.0f / sum;
            #pragma unroll
            for (int k = 0; k < KSZ; k++)
                d_Kern[(b * C_ + c) * KSZ + k] = e[k] * inv;
        }
        return;
    }

    // ---- L-branch conv1d: output channel o = blockIdx.x ----
    const int o = blockIdx.x;
    const int lane = tid & 31;
    const int wrp  = tid >> 5;

    for (int i = tid; i < C_ * PSROW; i += 128) ps[i] = 0.f;
    __syncthreads();
    const float4* pp = reinterpret_cast<const float4*>(d_pooled + b * C_ * T_);
    for (int i = tid; i < C_ * T_ / 4; i += 128) {
        float4 v = pp[i];
        int e0 = i * 4;
        int c = e0 >> 4, t = e0 & 15;
        float* r = &ps[c * PSROW + PAD + t];
        r[0] = v.x; r[1] = v.y; r[2] = v.z; r[3] = v.w;
    }
    __syncthreads();

    float acc[T_];
    #pragma unroll
    for (int t = 0; t < T_; t++) acc[t] = 0.f;

    const float* w = Wl1 + o * (C_ * KSZ);
    #pragma unroll
    for (int ii = 0; ii < 2; ii++) {
        const int i = tid * 2 + ii;
        float wk[KSZ];
        #pragma unroll
        for (int k = 0; k < KSZ; k++) wk[k] = w[i * KSZ + k];
        float pv[T_ + 2 * PAD];
        #pragma unroll
        for (int j = 0; j < T_ + 2 * PAD; j++) pv[j] = ps[i * PSROW + j];
        #pragma unroll
        for (int t = 0; t < T_; t++) {
            #pragma unroll
            for (int k = 0; k < KSZ; k++)
                acc[t] += wk[k] * pv[t + k];
        }
    }

    #pragma unroll
    for (int off = 16; off > 0; off >>= 1) {
        #pragma unroll
        for (int t = 0; t < T_; t++)
            acc[t] += __shfl_xor_sync(0xffffffffu, acc[t], off);
    }
    if (lane == 0) {
        #pragma unroll
        for (int t = 0; t < T_; t++) red[wrp][t] = acc[t];
    }
    __syncthreads();
    if (tid < T_) {
        float s = red[0][tid] + red[1][tid] + red[2][tid] + red[3][tid];
        d_Yt[(b * T_ + tid) * 64 + o] = tanhf(s);   // transposed store
    }
}

// ---------------------------------------------------------------------------
// Kernel 3: main. One block per (b,c), 196 threads (one float4 lane each).
//   All 16 x-slice loads issued up front (MLP=16, no gate dependency);
//   gates computed concurrently by threads 0..15; sync; scale + 7-tap conv;
//   plain stores.
// ---------------------------------------------------------------------------
__global__ void __launch_bounds__(196)
tam_main_kernel(const float* __restrict__ x, float* __restrict__ out,
                const float* __restrict__ Wl2)   // [256][64]
{
    __shared__ float lrs[T_];
    const int bc  = blockIdx.x;
    const int b   = bc >> 8;
    const int c   = bc & (C_ - 1);
    const int tid = threadIdx.x;     // 0..195

    const size_t base = (size_t)(b * T_ * C_ + c) * HW4_ + tid;   // t=0 slice
    const int tstride = C_ * HW4_;
    const float4* xp = reinterpret_cast<const float4*>(x) + base;
    float4*       op = reinterpret_cast<float4*>(out) + base;

    // front-batched, ungated x loads — independent of gate math below
    float4 g[T_];
    #pragma unroll
    for (int t = 0; t < T_; t++) g[t] = xp[t * tstride];

    // gates (threads 0..15), overlapped with the x-load latency
    if (tid < T_) {
        const float4* wv = reinterpret_cast<const float4*>(Wl2 + c * 64);
        const float4* yv = reinterpret_cast<const float4*>(d_Yt + (b * T_ + tid) * 64);
        float acc = 0.f;
        #pragma unroll
        for (int q = 0; q < 16; q++) {
            float4 wq = wv[q], yq = yv[q];
            acc += wq.x * yq.x + wq.y * yq.y + wq.z * yq.z + wq.w * yq.w;
        }
        lrs[tid] = 1.0f / (1.0f + expf(-acc));
    }

    float kr[KSZ];
    #pragma unroll
    for (int k = 0; k < KSZ; k++) kr[k] = d_Kern[bc * KSZ + k];

    __syncthreads();

    #pragma unroll
    for (int t = 0; t < T_; t++) {
        float l = lrs[t];
        g[t].x *= l; g[t].y *= l; g[t].z *= l; g[t].w *= l;
    }

    #pragma unroll
    for (int t = 0; t < T_; t++) {
        float4 a; a.x = a.y = a.z = a.w = 0.f;
        #pragma unroll
        for (int k = 0; k < KSZ; k++) {
            int u = t + k - PAD;
            if (u >= 0 && u < T_) {          // constant-folded
                float kk = kr[k];
                a.x += kk * g[u].x;
                a.y += kk * g[u].y;
                a.z += kk * g[u].z;
                a.w += kk * g[u].w;
            }
        }
        op[t * tstride] = a;
    }
}

// ---------------------------------------------------------------------------
extern "C" void kernel_launch(void* const* d_in, const int* in_sizes, int n_in,
                              void* d_out, int out_size) {
    const float* x   = (const float*)d_in[0];
    const float* W1  = (const float*)d_in[1];
    const float* W2  = (const float*)d_in[2];
    const float* Wl1 = (const float*)d_in[3];
    const float* Wl2 = (const float*)d_in[4];
    float* out = (float*)d_out;

    pool_kernel<<<(B_ * T_ * C_) / 8, 256>>>(x);
    coeff_kernel<<<dim3(65, B_), 128>>>(Wl1, W1, W2);
    tam_main_kernel<<<NBC, 196>>>(x, out, Wl2);
}